// round 2
// baseline (speedup 1.0000x reference)
#include <cuda_runtime.h>

#define HH 16
#define VV 4
#define BB 512
#define SS 8192
#define GPB 8               // batch groups (of 16 lanes) per block
#define NTHREADS (GPB*16)   // 128
#define NBLOCKS (BB/GPB)    // 64

__device__ float g_ench[BB*HH];
__device__ float g_loss[BB];

__device__ __forceinline__ float tanh_ap(float x){ float y; asm("tanh.approx.f32 %0, %1;" : "=f"(y) : "f"(x)); return y; }
__device__ __forceinline__ float ex2_ap(float x){ float y; asm("ex2.approx.f32 %0, %1;" : "=f"(y) : "f"(x)); return y; }
__device__ __forceinline__ float lg2_ap(float x){ float y; asm("lg2.approx.f32 %0, %1;" : "=f"(y) : "f"(x)); return y; }
__device__ __forceinline__ float sigm(float x){ return fmaf(tanh_ap(0.5f*x), 0.5f, 0.5f); }
__device__ __forceinline__ float f4c(float4 v, int u){ return u==0?v.x:(u==1?v.y:(u==2?v.z:v.w)); }
__device__ __forceinline__ float pick4(float w0,float w1,float w2,float w3,int i){
    // i in {-1,0,1,2,3}; -1 -> 0 (decoder first-step x = zeros)
    return (i==0)?w0:((i==1)?w1:((i==2)?w2:((i==3)?w3:0.f)));
}

// ---------------------------------------------------------------------------
// Encoder: h_{t+1} = GRU(gt[:, :, t], h_t). Writes final hidden to g_ench.
// ---------------------------------------------------------------------------
__global__ void __launch_bounds__(NTHREADS, 1)
enc_kernel(const float* __restrict__ gt,
           const float* __restrict__ Wih, const float* __restrict__ Whh,
           const float* __restrict__ bih, const float* __restrict__ bhh)
{
    const int j = threadIdx.x & 15;
    const int b = blockIdx.x * GPB + (threadIdx.x >> 4);

    float wxr[4], wxz[4], wxn[4];
#pragma unroll
    for (int v = 0; v < 4; v++) {
        wxr[v] = Wih[j*4 + v];
        wxz[v] = Wih[(16+j)*4 + v];
        wxn[v] = Wih[(32+j)*4 + v];
    }
    float whr[16], whz[16], whn[16];
#pragma unroll
    for (int k = 0; k < 16; k++) {
        whr[k] = Whh[j*16 + k];
        whz[k] = Whh[(16+j)*16 + k];
        whn[k] = Whh[(32+j)*16 + k];
    }
    const float br  = bih[j]    + bhh[j];
    const float bz  = bih[16+j] + bhh[16+j];
    const float bin_ = bih[32+j];
    const float bhn  = bhh[32+j];

    float h[16];
#pragma unroll
    for (int k = 0; k < 16; k++) h[k] = 0.f;
    float hme = 0.f;

    const float4* gp = (const float4*)(gt + (size_t)b * VV * SS);
    const int SQ = SS / 4;

    for (int t4 = 0; t4 < SQ; ++t4) {
        float4 xv0 = gp[t4];
        float4 xv1 = gp[SQ   + t4];
        float4 xv2 = gp[2*SQ + t4];
        float4 xv3 = gp[3*SQ + t4];
#pragma unroll
        for (int u = 0; u < 4; u++) {
            float x0 = f4c(xv0, u), x1 = f4c(xv1, u), x2 = f4c(xv2, u), x3 = f4c(xv3, u);
            // gi (x path) — independent of h, schedules early
            float gir = br, giz = bz, gin = bin_;
            gir = fmaf(x0, wxr[0], gir); gir = fmaf(x1, wxr[1], gir);
            gir = fmaf(x2, wxr[2], gir); gir = fmaf(x3, wxr[3], gir);
            giz = fmaf(x0, wxz[0], giz); giz = fmaf(x1, wxz[1], giz);
            giz = fmaf(x2, wxz[2], giz); giz = fmaf(x3, wxz[3], giz);
            gin = fmaf(x0, wxn[0], gin); gin = fmaf(x1, wxn[1], gin);
            gin = fmaf(x2, wxn[2], gin); gin = fmaf(x3, wxn[3], gin);
            // gh (h path)
            float ghr = 0.f, ghz = 0.f, ghn = bhn;
            float ghr2 = 0.f, ghz2 = 0.f, ghn2 = 0.f;
#pragma unroll
            for (int k = 0; k < 16; k += 2) {
                ghr  = fmaf(h[k],   whr[k],   ghr);
                ghr2 = fmaf(h[k+1], whr[k+1], ghr2);
                ghz  = fmaf(h[k],   whz[k],   ghz);
                ghz2 = fmaf(h[k+1], whz[k+1], ghz2);
                ghn  = fmaf(h[k],   whn[k],   ghn);
                ghn2 = fmaf(h[k+1], whn[k+1], ghn2);
            }
            ghr += ghr2; ghz += ghz2; ghn += ghn2;
            float r = sigm(gir + ghr);
            float z = sigm(giz + ghz);
            float n = tanh_ap(fmaf(r, ghn, gin));
            hme = fmaf(z, hme - n, n);      // (1-z)*n + z*h
#pragma unroll
            for (int k = 0; k < 16; k++)
                h[k] = __shfl_sync(0xffffffffu, hme, k, 16);
        }
    }
    g_ench[b*HH + j] = hme;
}

// ---------------------------------------------------------------------------
// Decoder: argmax-feedback GRU + NLL loss accumulation per batch element.
// ---------------------------------------------------------------------------
__global__ void __launch_bounds__(NTHREADS, 1)
dec_kernel(const float* __restrict__ gt,
           const float* __restrict__ Wih, const float* __restrict__ Whh,
           const float* __restrict__ bih, const float* __restrict__ bhh,
           const float* __restrict__ oW,  const float* __restrict__ ob)
{
    const int j = threadIdx.x & 15;
    const int b = blockIdx.x * GPB + (threadIdx.x >> 4);
    const int v = j & 3;       // output logit owned by this lane
    const int seg = j >> 2;    // k-segment for distributed out matvec

    // one-hot x -> Wih column selects
    float dxr[4], dxz[4], dxn[4];
#pragma unroll
    for (int c = 0; c < 4; c++) {
        dxr[c] = Wih[j*4 + c];
        dxz[c] = Wih[(16+j)*4 + c];
        dxn[c] = Wih[(32+j)*4 + c];
    }
    float whr[16], whz[16], whn[16];
#pragma unroll
    for (int k = 0; k < 16; k++) {
        whr[k] = Whh[j*16 + k];
        whz[k] = Whh[(16+j)*16 + k];
        whn[k] = Whh[(32+j)*16 + k];
    }
    const float br  = bih[j]    + bhh[j];
    const float bz  = bih[16+j] + bhh[16+j];
    const float bin_ = bih[32+j];
    const float bhn  = bhh[32+j];

    float owj[4];
#pragma unroll
    for (int kk = 0; kk < 4; kk++) owj[kk] = oW[v*16 + seg*4 + kk];
    const float obv = ob[v];

    float hme = g_ench[b*HH + j];
    float h[16];
#pragma unroll
    for (int k = 0; k < 16; k++)
        h[k] = __shfl_sync(0xffffffffu, hme, k, 16);

    int top = -1;          // first step: x = zeros
    float lacc = 0.f;

    const float4* gp = (const float4*)(gt + (size_t)b * VV * SS);
    const int SQ = SS / 4;
    const float LOG2E = 1.4426950408889634f;
    const float LN2   = 0.6931471805599453f;

    for (int t4 = 0; t4 < SQ; ++t4) {
        float4 xv0 = gp[t4];
        float4 xv1 = gp[SQ   + t4];
        float4 xv2 = gp[2*SQ + t4];
        float4 xv3 = gp[3*SQ + t4];
#pragma unroll
        for (int u = 0; u < 4; u++) {
            // ---- GRU cell with one-hot x (column select) ----
            float gir = br  + pick4(dxr[0], dxr[1], dxr[2], dxr[3], top);
            float giz = bz  + pick4(dxz[0], dxz[1], dxz[2], dxz[3], top);
            float gin = bin_ + pick4(dxn[0], dxn[1], dxn[2], dxn[3], top);
            float ghr = 0.f, ghz = 0.f, ghn = bhn;
            float ghr2 = 0.f, ghz2 = 0.f, ghn2 = 0.f;
#pragma unroll
            for (int k = 0; k < 16; k += 2) {
                ghr  = fmaf(h[k],   whr[k],   ghr);
                ghr2 = fmaf(h[k+1], whr[k+1], ghr2);
                ghz  = fmaf(h[k],   whz[k],   ghz);
                ghz2 = fmaf(h[k+1], whz[k+1], ghz2);
                ghn  = fmaf(h[k],   whn[k],   ghn);
                ghn2 = fmaf(h[k+1], whn[k+1], ghn2);
            }
            ghr += ghr2; ghz += ghz2; ghn += ghn2;
            float r = sigm(gir + ghr);
            float z = sigm(giz + ghz);
            float n = tanh_ap(fmaf(r, ghn, gin));
            hme = fmaf(z, hme - n, n);
#pragma unroll
            for (int k = 0; k < 16; k++)
                h[k] = __shfl_sync(0xffffffffu, hme, k, 16);

            // ---- out = h @ oW^T + ob : distributed 4 FMA + 2 shfl reduce ----
            float part = 0.f;
#pragma unroll
            for (int kk = 0; kk < 4; kk++)
                part = fmaf(h[seg*4 + kk], owj[kk], part);
            part += __shfl_xor_sync(0xffffffffu, part, 4, 16);
            part += __shfl_xor_sync(0xffffffffu, part, 8, 16);
            float outv = part + obv;      // lane holds logit for class v = j&3

            // ---- argmax over 4 classes (first-max tie rule) ----
            float mval = outv; int midx = v;
            {
                float o  = __shfl_xor_sync(0xffffffffu, mval, 1, 16);
                int   oi = __shfl_xor_sync(0xffffffffu, midx, 1, 16);
                if (o > mval || (o == mval && oi < midx)) { mval = o; midx = oi; }
            }
            {
                float o  = __shfl_xor_sync(0xffffffffu, mval, 2, 16);
                int   oi = __shfl_xor_sync(0xffffffffu, midx, 2, 16);
                if (o > mval || (o == mval && oi < midx)) { mval = o; midx = oi; }
            }

            // ---- logsumexp (stable) ----
            float e = ex2_ap((outv - mval) * LOG2E);
            e += __shfl_xor_sync(0xffffffffu, e, 1, 16);
            e += __shfl_xor_sync(0xffffffffu, e, 2, 16);
            float lse = lg2_ap(e) * LN2;

            // ---- target = argmax(gt[t, b, :]) ----
            float x0 = f4c(xv0, u), x1 = f4c(xv1, u), x2 = f4c(xv2, u), x3 = f4c(xv3, u);
            int tgt = 0; float tv = x0;
            if (x1 > tv) { tv = x1; tgt = 1; }
            if (x2 > tv) { tv = x2; tgt = 2; }
            if (x3 > tv) { tv = x3; tgt = 3; }

            float out_t = __shfl_sync(0xffffffffu, outv, tgt, 16);
            lacc += (mval + lse - out_t);   // -= logp[tgt]

            top = midx;                      // feedback for next step
        }
    }
    if (j == 0) g_loss[b] = lacc;
}

// ---------------------------------------------------------------------------
// Output zeroing + deterministic loss reduction
// ---------------------------------------------------------------------------
__global__ void zero_kernel(float* __restrict__ out, long long n)
{
    long long i = (long long)blockIdx.x * blockDim.x + threadIdx.x;
    long long stride = (long long)gridDim.x * blockDim.x;
    for (; i < n; i += stride) out[i] = 0.f;
}

__global__ void fin_kernel(float* __restrict__ out)
{
    __shared__ float s[BB];
    s[threadIdx.x] = g_loss[threadIdx.x];
    __syncthreads();
#pragma unroll
    for (int st = BB/2; st > 0; st >>= 1) {
        if ((int)threadIdx.x < st) s[threadIdx.x] += s[threadIdx.x + st];
        __syncthreads();
    }
    if (threadIdx.x == 0) out[0] = s[0] * (1.f / (float)BB);
}

// ---------------------------------------------------------------------------
extern "C" void kernel_launch(void* const* d_in, const int* in_sizes, int n_in,
                              void* d_out, int out_size)
{
    const float* gt    = (const float*)d_in[0];
    const float* eWih  = (const float*)d_in[1];
    const float* eWhh  = (const float*)d_in[2];
    const float* ebih  = (const float*)d_in[3];
    const float* ebhh  = (const float*)d_in[4];
    const float* dWih  = (const float*)d_in[5];
    const float* dWhh  = (const float*)d_in[6];
    const float* dbih  = (const float*)d_in[7];
    const float* dbhh  = (const float*)d_in[8];
    const float* oW    = (const float*)d_in[9];
    const float* ob    = (const float*)d_in[10];
    float* out = (float*)d_out;

    zero_kernel<<<1024, 256>>>(out, (long long)out_size);
    enc_kernel<<<NBLOCKS, NTHREADS>>>(gt, eWih, eWhh, ebih, ebhh);
    dec_kernel<<<NBLOCKS, NTHREADS>>>(gt, dWih, dWhh, dbih, dbhh, oW, ob);
    fin_kernel<<<1, BB>>>(out);
}

// round 3
// speedup vs baseline: 1.7313x; 1.7313x over previous
#include <cuda_runtime.h>

#define HH 16
#define VV 4
#define BB 512
#define SS 8192
#define WPB 4                 // warps per block, 1 batch element per warp
#define NTHREADS (WPB*32)     // 128
#define NBLOCKS (BB/WPB)      // 128 blocks -> <=1 block/SM

__device__ float g_ench[BB*HH];
__device__ float g_loss[BB];

typedef unsigned long long u64;

__device__ __forceinline__ float tanh_ap(float x){ float y; asm("tanh.approx.f32 %0, %1;" : "=f"(y) : "f"(x)); return y; }
__device__ __forceinline__ float ex2_ap(float x){ float y; asm("ex2.approx.f32 %0, %1;" : "=f"(y) : "f"(x)); return y; }
__device__ __forceinline__ float lg2_ap(float x){ float y; asm("lg2.approx.f32 %0, %1;" : "=f"(y) : "f"(x)); return y; }
__device__ __forceinline__ u64 pk(float lo, float hi){ u64 d; asm("mov.b64 %0,{%1,%2};" : "=l"(d) : "f"(lo), "f"(hi)); return d; }
__device__ __forceinline__ u64 fma2(u64 a, u64 b, u64 c){ u64 d; asm("fma.rn.f32x2 %0,%1,%2,%3;" : "=l"(d) : "l"(a), "l"(b), "l"(c)); return d; }
__device__ __forceinline__ u64 add2(u64 a, u64 b){ u64 d; asm("add.rn.f32x2 %0,%1,%2;" : "=l"(d) : "l"(a), "l"(b)); return d; }
__device__ __forceinline__ float hadd(u64 a){ float x,y; asm("mov.b64 {%0,%1},%2;" : "=f"(x), "=f"(y) : "l"(a)); return x+y; }
__device__ __forceinline__ float f4c(float4 v, int u){ return u==0?v.x:(u==1?v.y:(u==2?v.z:v.w)); }

__device__ __forceinline__ void sts_h(unsigned addr, float v){
    asm volatile("st.shared.b32 [%0], %1;" :: "r"(addr), "f"(v) : "memory");
}
__device__ __forceinline__ void ldh4(unsigned base, u64* hp){
    asm volatile("ld.shared.v2.b64 {%0,%1},[%2];"    : "=l"(hp[0]), "=l"(hp[1]) : "r"(base)      : "memory");
    asm volatile("ld.shared.v2.b64 {%0,%1},[%2+16];" : "=l"(hp[2]), "=l"(hp[3]) : "r"(base)      : "memory");
    asm volatile("ld.shared.v2.b64 {%0,%1},[%2+32];" : "=l"(hp[4]), "=l"(hp[5]) : "r"(base)      : "memory");
    asm volatile("ld.shared.v2.b64 {%0,%1},[%2+48];" : "=l"(hp[6]), "=l"(hp[7]) : "r"(base)      : "memory");
}
__device__ __forceinline__ void pf_l1(const void* p){
    asm volatile("prefetch.global.L1 [%0];" :: "l"(p));
}

// ---------------------------------------------------------------------------
// Encoder: one batch element per warp, h distributed one unit per lane (j=lane&15),
// broadcast via shared memory, gates in fma.f32x2.
// ---------------------------------------------------------------------------
__global__ void __launch_bounds__(NTHREADS, 1)
enc_kernel(const float* __restrict__ gt,
           const float* __restrict__ Wih, const float* __restrict__ Whh,
           const float* __restrict__ bih, const float* __restrict__ bhh)
{
    __shared__ __align__(16) float sh[WPB*16];
    const int lane = threadIdx.x & 31;
    const int w    = threadIdx.x >> 5;
    const int j    = lane & 15;
    const int b    = blockIdx.x * WPB + w;
    const unsigned hbase = (unsigned)__cvta_generic_to_shared(&sh[w*16]);

    // weights packed into f32x2 pairs; r,z gate pre-scaled by 0.5 (tanh-sigmoid)
    u64 wr[8], wz[8], wn[8];
#pragma unroll
    for (int p = 0; p < 8; p++) {
        wr[p] = pk(0.5f*Whh[j*16 + 2*p],      0.5f*Whh[j*16 + 2*p+1]);
        wz[p] = pk(0.5f*Whh[(16+j)*16 + 2*p], 0.5f*Whh[(16+j)*16 + 2*p+1]);
        wn[p] = pk(     Whh[(32+j)*16 + 2*p],      Whh[(32+j)*16 + 2*p+1]);
    }
    const u64 xr01 = pk(0.5f*Wih[j*4+0],      0.5f*Wih[j*4+1]);
    const u64 xr23 = pk(0.5f*Wih[j*4+2],      0.5f*Wih[j*4+3]);
    const u64 xz01 = pk(0.5f*Wih[(16+j)*4+0], 0.5f*Wih[(16+j)*4+1]);
    const u64 xz23 = pk(0.5f*Wih[(16+j)*4+2], 0.5f*Wih[(16+j)*4+3]);
    const u64 xn01 = pk(     Wih[(32+j)*4+0],      Wih[(32+j)*4+1]);
    const u64 xn23 = pk(     Wih[(32+j)*4+2],      Wih[(32+j)*4+3]);
    const u64 brpk = pk(0.5f*(bih[j]    + bhh[j]),    0.f);
    const u64 bzpk = pk(0.5f*(bih[16+j] + bhh[16+j]), 0.f);
    const u64 binpk = pk(bih[32+j], 0.f);
    const u64 bhnpk = pk(bhh[32+j], 0.f);
    const u64 z2 = 0ULL;

    float hme = 0.f;
    sh[w*16 + j] = 0.f;
    __syncthreads();

    const float4* gp = (const float4*)(gt + (size_t)b * VV * SS);
    const int SQ = SS / 4;

    for (int t4 = 0; t4 < SQ; ++t4) {
        int t4p = t4 + 8 < SQ ? t4 + 8 : SQ - 1;
        pf_l1(gp + t4p); pf_l1(gp + SQ + t4p); pf_l1(gp + 2*SQ + t4p); pf_l1(gp + 3*SQ + t4p);
        float4 xv0 = gp[t4], xv1 = gp[SQ + t4], xv2 = gp[2*SQ + t4], xv3 = gp[3*SQ + t4];
#pragma unroll
        for (int u = 0; u < 4; u++) {
            u64 px01 = pk(f4c(xv0,u), f4c(xv1,u));
            u64 px23 = pk(f4c(xv2,u), f4c(xv3,u));
            u64 hp[8];
            ldh4(hbase, hp);

            // r gate (pre-halved)
            u64 ra = fma2(px23, xr23, fma2(px01, xr01, brpk));
            ra = fma2(hp[0], wr[0], ra); ra = fma2(hp[1], wr[1], ra);
            ra = fma2(hp[2], wr[2], ra); ra = fma2(hp[3], wr[3], ra);
            u64 rb = fma2(hp[4], wr[4], z2); rb = fma2(hp[5], wr[5], rb);
            rb = fma2(hp[6], wr[6], rb);     rb = fma2(hp[7], wr[7], rb);
            float sr = hadd(add2(ra, rb));
            // z gate (pre-halved)
            u64 za = fma2(px23, xz23, fma2(px01, xz01, bzpk));
            za = fma2(hp[0], wz[0], za); za = fma2(hp[1], wz[1], za);
            za = fma2(hp[2], wz[2], za); za = fma2(hp[3], wz[3], za);
            u64 zb = fma2(hp[4], wz[4], z2); zb = fma2(hp[5], wz[5], zb);
            zb = fma2(hp[6], wz[6], zb);     zb = fma2(hp[7], wz[7], zb);
            float sz = hadd(add2(za, zb));
            // n gate: gh (incl bhn) and gi kept separate
            u64 na = fma2(hp[0], wn[0], bhnpk); na = fma2(hp[1], wn[1], na);
            na = fma2(hp[2], wn[2], na);        na = fma2(hp[3], wn[3], na);
            u64 nb = fma2(hp[4], wn[4], z2); nb = fma2(hp[5], wn[5], nb);
            nb = fma2(hp[6], wn[6], nb);     nb = fma2(hp[7], wn[7], nb);
            float ghn = hadd(add2(na, nb));
            float gin = hadd(fma2(px23, xn23, fma2(px01, xn01, binpk)));

            float tr = tanh_ap(sr);               // r = 0.5 + 0.5*tr
            float tz = tanh_ap(sz);
            float zg  = fmaf(tz,  0.5f, 0.5f);    // z
            float omz = fmaf(tz, -0.5f, 0.5f);    // 1-z
            float zh  = zg * hme;                 // off n-path
            float gh2 = 0.5f * ghn;
            float base = gin + gh2;
            float n = tanh_ap(fmaf(tr, gh2, base));
            hme = fmaf(n, omz, zh);
            sts_h(hbase + j*4, hme);
        }
    }
    if (lane < 16) g_ench[b*HH + j] = hme;
}

// ---------------------------------------------------------------------------
// Decoder: argmax feedback + NLL. One batch per warp. Each lane computes a
// FULL logit (v = j&3); argmax via 4 independent width-4 shuffles + local tree.
// ---------------------------------------------------------------------------
__global__ void __launch_bounds__(NTHREADS, 1)
dec_kernel(const float* __restrict__ gt,
           const float* __restrict__ Wih, const float* __restrict__ Whh,
           const float* __restrict__ bih, const float* __restrict__ bhh,
           const float* __restrict__ oW,  const float* __restrict__ ob)
{
    __shared__ __align__(16) float sh[WPB*16];
    const int lane = threadIdx.x & 31;
    const int w    = threadIdx.x >> 5;
    const int j    = lane & 15;
    const int b    = blockIdx.x * WPB + w;
    const int v    = j & 3;
    const unsigned hbase = (unsigned)__cvta_generic_to_shared(&sh[w*16]);

    u64 wr[8], wz[8], wn[8], ow[8];
#pragma unroll
    for (int p = 0; p < 8; p++) {
        wr[p] = pk(0.5f*Whh[j*16 + 2*p],      0.5f*Whh[j*16 + 2*p+1]);
        wz[p] = pk(0.5f*Whh[(16+j)*16 + 2*p], 0.5f*Whh[(16+j)*16 + 2*p+1]);
        wn[p] = pk(     Whh[(32+j)*16 + 2*p],      Whh[(32+j)*16 + 2*p+1]);
        ow[p] = pk(oW[v*16 + 2*p], oW[v*16 + 2*p+1]);
    }
    // one-hot x -> column selects (r,z pre-halved)
    float dxr[4], dxz[4], dxn[4];
#pragma unroll
    for (int c = 0; c < 4; c++) {
        dxr[c] = 0.5f*Wih[j*4 + c];
        dxz[c] = 0.5f*Wih[(16+j)*4 + c];
        dxn[c] =      Wih[(32+j)*4 + c];
    }
    const float br  = 0.5f*(bih[j]    + bhh[j]);
    const float bz  = 0.5f*(bih[16+j] + bhh[16+j]);
    const float bin_ = bih[32+j];
    const u64 bhnpk = pk(bhh[32+j], 0.f);
    const u64 obpk  = pk(ob[v], 0.f);
    const u64 z2 = 0ULL;

    float cr = br, cz = bz, cn = bin_;   // bias + x-contribution (x=0 at t=0)
    float hme = g_ench[b*HH + j];
    sh[w*16 + j] = hme;
    __syncthreads();

    float lacc = 0.f;
    const float4* gp = (const float4*)(gt + (size_t)b * VV * SS);
    const int SQ = SS / 4;
    const float LOG2E = 1.4426950408889634f;
    const float LN2   = 0.6931471805599453f;

    for (int t4 = 0; t4 < SQ; ++t4) {
        int t4p = t4 + 8 < SQ ? t4 + 8 : SQ - 1;
        pf_l1(gp + t4p); pf_l1(gp + SQ + t4p); pf_l1(gp + 2*SQ + t4p); pf_l1(gp + 3*SQ + t4p);
        float4 xv0 = gp[t4], xv1 = gp[SQ + t4], xv2 = gp[2*SQ + t4], xv3 = gp[3*SQ + t4];
#pragma unroll
        for (int u = 0; u < 4; u++) {
            u64 hp[8];
            ldh4(hbase, hp);

            u64 ra = fma2(hp[0], wr[0], z2); ra = fma2(hp[1], wr[1], ra);
            ra = fma2(hp[2], wr[2], ra);     ra = fma2(hp[3], wr[3], ra);
            u64 rb = fma2(hp[4], wr[4], z2); rb = fma2(hp[5], wr[5], rb);
            rb = fma2(hp[6], wr[6], rb);     rb = fma2(hp[7], wr[7], rb);
            float sr = hadd(add2(ra, rb)) + cr;

            u64 za = fma2(hp[0], wz[0], z2); za = fma2(hp[1], wz[1], za);
            za = fma2(hp[2], wz[2], za);     za = fma2(hp[3], wz[3], za);
            u64 zb = fma2(hp[4], wz[4], z2); zb = fma2(hp[5], wz[5], zb);
            zb = fma2(hp[6], wz[6], zb);     zb = fma2(hp[7], wz[7], zb);
            float sz = hadd(add2(za, zb)) + cz;

            u64 na = fma2(hp[0], wn[0], bhnpk); na = fma2(hp[1], wn[1], na);
            na = fma2(hp[2], wn[2], na);        na = fma2(hp[3], wn[3], na);
            u64 nb = fma2(hp[4], wn[4], z2); nb = fma2(hp[5], wn[5], nb);
            nb = fma2(hp[6], wn[6], nb);     nb = fma2(hp[7], wn[7], nb);
            float ghn = hadd(add2(na, nb));

            float tr = tanh_ap(sr);
            float tz = tanh_ap(sz);
            float zg  = fmaf(tz,  0.5f, 0.5f);
            float omz = fmaf(tz, -0.5f, 0.5f);
            float zh  = zg * hme;
            float gh2 = 0.5f * ghn;
            float base = cn + gh2;
            float n = tanh_ap(fmaf(tr, gh2, base));
            hme = fmaf(n, omz, zh);
            sts_h(hbase + j*4, hme);

            // full logit for class v in every lane
            u64 oa = fma2(hp[0], ow[0], obpk); // NOTE: uses h_t ... must use h_{t+1}!
            (void)oa;
            // --- recompute with fresh h (see below) ---
            u64 hq[8];
            ldh4(hbase, hq);
            u64 qa = fma2(hq[0], ow[0], obpk); qa = fma2(hq[1], ow[1], qa);
            qa = fma2(hq[2], ow[2], qa);       qa = fma2(hq[3], ow[3], qa);
            u64 qb = fma2(hq[4], ow[4], z2); qb = fma2(hq[5], ow[5], qb);
            qb = fma2(hq[6], ow[6], qb);     qb = fma2(hq[7], ow[7], qb);
            float outv = hadd(add2(qa, qb));

            float l0 = __shfl_sync(0xffffffffu, outv, 0, 4);
            float l1 = __shfl_sync(0xffffffffu, outv, 1, 4);
            float l2 = __shfl_sync(0xffffffffu, outv, 2, 4);
            float l3 = __shfl_sync(0xffffffffu, outv, 3, 4);

            // argmax (first-max tie rule)
            bool p01 = l1 > l0;  float m01 = p01 ? l1 : l0;
            bool p23 = l3 > l2;  float m23 = p23 ? l3 : l2;
            bool phi = m23 > m01; float mval = phi ? m23 : m01;
            // next-step x contributions
            float xr_ = phi ? (p23 ? dxr[3] : dxr[2]) : (p01 ? dxr[1] : dxr[0]);
            float xz_ = phi ? (p23 ? dxz[3] : dxz[2]) : (p01 ? dxz[1] : dxz[0]);
            float xn_ = phi ? (p23 ? dxn[3] : dxn[2]) : (p01 ? dxn[1] : dxn[0]);
            cr = br + xr_; cz = bz + xz_; cn = bin_ + xn_;

            // logsumexp over the 4 logits (lane-parallel, width-4 xor reduce)
            float e = ex2_ap((outv - mval) * LOG2E);
            e += __shfl_xor_sync(0xffffffffu, e, 1, 4);
            e += __shfl_xor_sync(0xffffffffu, e, 2, 4);
            float lse = lg2_ap(e) * LN2;

            // target = argmax(gt[t,b,:]) (first-max)
            float x0 = f4c(xv0,u), x1 = f4c(xv1,u), x2 = f4c(xv2,u), x3 = f4c(xv3,u);
            bool q01 = x1 > x0;  float t01 = q01 ? x1 : x0;
            bool q23 = x3 > x2;  float t23 = q23 ? x3 : x2;
            bool qhi = t23 > t01;
            float out_t = qhi ? (q23 ? l3 : l2) : (q01 ? l1 : l0);

            lacc += (mval + lse - out_t);
        }
    }
    if (lane == 0) g_loss[b] = lacc;
}

// ---------------------------------------------------------------------------
__global__ void zero_kernel(float* __restrict__ out, long long n)
{
    long long i = (long long)blockIdx.x * blockDim.x + threadIdx.x;
    long long stride = (long long)gridDim.x * blockDim.x;
    for (; i < n; i += stride) out[i] = 0.f;
}

__global__ void fin_kernel(float* __restrict__ out)
{
    __shared__ float s[BB];
    s[threadIdx.x] = g_loss[threadIdx.x];
    __syncthreads();
#pragma unroll
    for (int st = BB/2; st > 0; st >>= 1) {
        if ((int)threadIdx.x < st) s[threadIdx.x] += s[threadIdx.x + st];
        __syncthreads();
    }
    if (threadIdx.x == 0) out[0] = s[0] * (1.f / (float)BB);
}

// ---------------------------------------------------------------------------
extern "C" void kernel_launch(void* const* d_in, const int* in_sizes, int n_in,
                              void* d_out, int out_size)
{
    const float* gt   = (const float*)d_in[0];
    const float* eWih = (const float*)d_in[1];
    const float* eWhh = (const float*)d_in[2];
    const float* ebih = (const float*)d_in[3];
    const float* ebhh = (const float*)d_in[4];
    const float* dWih = (const float*)d_in[5];
    const float* dWhh = (const float*)d_in[6];
    const float* dbih = (const float*)d_in[7];
    const float* dbhh = (const float*)d_in[8];
    const float* oW   = (const float*)d_in[9];
    const float* ob   = (const float*)d_in[10];
    float* out = (float*)d_out;

    zero_kernel<<<1024, 256>>>(out, (long long)out_size);
    enc_kernel<<<NBLOCKS, NTHREADS>>>(gt, eWih, eWhh, ebih, ebhh);
    dec_kernel<<<NBLOCKS, NTHREADS>>>(gt, dWih, dWhh, dbih, dbhh, oW, ob);
    fin_kernel<<<1, BB>>>(out);
}

// round 4
// speedup vs baseline: 1.7322x; 1.0005x over previous
#include <cuda_runtime.h>

#define HH 16
#define VV 4
#define BB 512
#define SS 8192
#define WPB 4                 // warps per block, 1 batch element per warp
#define NTHREADS (WPB*32)     // 128
#define NBLOCKS (BB/WPB)      // 128 blocks

__device__ float g_loss[BB];

typedef unsigned long long u64;

__device__ __forceinline__ float tanh_ap(float x){ float y; asm("tanh.approx.f32 %0, %1;" : "=f"(y) : "f"(x)); return y; }
__device__ __forceinline__ float ex2_ap(float x){ float y; asm("ex2.approx.f32 %0, %1;" : "=f"(y) : "f"(x)); return y; }
__device__ __forceinline__ float lg2_ap(float x){ float y; asm("lg2.approx.f32 %0, %1;" : "=f"(y) : "f"(x)); return y; }
__device__ __forceinline__ u64 pk(float lo, float hi){ u64 d; asm("mov.b64 %0,{%1,%2};" : "=l"(d) : "f"(lo), "f"(hi)); return d; }
__device__ __forceinline__ u64 fma2(u64 a, u64 b, u64 c){ u64 d; asm("fma.rn.f32x2 %0,%1,%2,%3;" : "=l"(d) : "l"(a), "l"(b), "l"(c)); return d; }
__device__ __forceinline__ u64 add2(u64 a, u64 b){ u64 d; asm("add.rn.f32x2 %0,%1,%2;" : "=l"(d) : "l"(a), "l"(b)); return d; }
__device__ __forceinline__ float hadd(u64 a){ float x,y; asm("mov.b64 {%0,%1},%2;" : "=f"(x), "=f"(y) : "l"(a)); return x+y; }
__device__ __forceinline__ float f4c(float4 v, int u){ return u==0?v.x:(u==1?v.y:(u==2?v.z:v.w)); }

__device__ __forceinline__ void sts_h(unsigned addr, float v){
    asm volatile("st.shared.b32 [%0], %1;" :: "r"(addr), "f"(v) : "memory");
}
__device__ __forceinline__ void ldh4(unsigned base, u64* hp){
    asm volatile("ld.shared.v2.b64 {%0,%1},[%2];"    : "=l"(hp[0]), "=l"(hp[1]) : "r"(base) : "memory");
    asm volatile("ld.shared.v2.b64 {%0,%1},[%2+16];" : "=l"(hp[2]), "=l"(hp[3]) : "r"(base) : "memory");
    asm volatile("ld.shared.v2.b64 {%0,%1},[%2+32];" : "=l"(hp[4]), "=l"(hp[5]) : "r"(base) : "memory");
    asm volatile("ld.shared.v2.b64 {%0,%1},[%2+48];" : "=l"(hp[6]), "=l"(hp[7]) : "r"(base) : "memory");
}
__device__ __forceinline__ void pf_l1(const void* p){
    asm volatile("prefetch.global.L1 [%0];" :: "l"(p));
}

// ---------------------------------------------------------------------------
// Fused encoder + decoder. One batch element per warp, h unit j = lane&15,
// broadcast via per-warp smem. fma.f32x2 throughout, depth-2 accumulator trees.
// ---------------------------------------------------------------------------
__global__ void __launch_bounds__(NTHREADS, 1)
fused_kernel(const float* __restrict__ gt,
             const float* __restrict__ eWih, const float* __restrict__ eWhh,
             const float* __restrict__ ebih, const float* __restrict__ ebhh,
             const float* __restrict__ dWih, const float* __restrict__ dWhh,
             const float* __restrict__ dbih, const float* __restrict__ dbhh,
             const float* __restrict__ oW,  const float* __restrict__ ob)
{
    __shared__ __align__(16) float sh[WPB*16];
    const int lane = threadIdx.x & 31;
    const int w    = threadIdx.x >> 5;
    const int j    = lane & 15;
    const int b    = blockIdx.x * WPB + w;
    const unsigned hbase = (unsigned)__cvta_generic_to_shared(&sh[w*16]);

    const float4* gp = (const float4*)(gt + (size_t)b * VV * SS);
    const int SQ = SS / 4;
    const u64 z2 = 0ULL;

    float hme = 0.f;

    // =================== ENCODER ===================
    {
        u64 wr[8], wz[8], wn[8];
#pragma unroll
        for (int p = 0; p < 8; p++) {
            wr[p] = pk(0.5f*eWhh[j*16 + 2*p],      0.5f*eWhh[j*16 + 2*p+1]);
            wz[p] = pk(0.5f*eWhh[(16+j)*16 + 2*p], 0.5f*eWhh[(16+j)*16 + 2*p+1]);
            wn[p] = pk(0.5f*eWhh[(32+j)*16 + 2*p], 0.5f*eWhh[(32+j)*16 + 2*p+1]);
        }
        const u64 xr01 = pk(0.5f*eWih[j*4+0],      0.5f*eWih[j*4+1]);
        const u64 xr23 = pk(0.5f*eWih[j*4+2],      0.5f*eWih[j*4+3]);
        const u64 xz01 = pk(0.5f*eWih[(16+j)*4+0], 0.5f*eWih[(16+j)*4+1]);
        const u64 xz23 = pk(0.5f*eWih[(16+j)*4+2], 0.5f*eWih[(16+j)*4+3]);
        const u64 xn01 = pk(     eWih[(32+j)*4+0],      eWih[(32+j)*4+1]);
        const u64 xn23 = pk(     eWih[(32+j)*4+2],      eWih[(32+j)*4+3]);
        const u64 brpk  = pk(0.5f*(ebih[j]    + ebhh[j]),    0.f);
        const u64 bzpk  = pk(0.5f*(ebih[16+j] + ebhh[16+j]), 0.f);
        const u64 binpk = pk(ebih[32+j], 0.f);
        const u64 bhnpk = pk(0.5f*ebhh[32+j], 0.f);

        u64 hp[8];
#pragma unroll
        for (int p = 0; p < 8; p++) hp[p] = 0ULL;   // h0 = 0

        for (int t4 = 0; t4 < SQ; ++t4) {
            int t4p = t4 + 8 < SQ ? t4 + 8 : SQ - 1;
            pf_l1(gp + t4p); pf_l1(gp + SQ + t4p); pf_l1(gp + 2*SQ + t4p); pf_l1(gp + 3*SQ + t4p);
            float4 xv0 = gp[t4], xv1 = gp[SQ + t4], xv2 = gp[2*SQ + t4], xv3 = gp[3*SQ + t4];
#pragma unroll
            for (int u = 0; u < 4; u++) {
                u64 px01 = pk(f4c(xv0,u), f4c(xv1,u));
                u64 px23 = pk(f4c(xv2,u), f4c(xv3,u));
                // x-path initializers (retire while hp settles)
                u64 ri0 = fma2(px01, xr01, brpk);
                u64 ri1 = fma2(px23, xr23, z2);
                u64 zi0 = fma2(px01, xz01, bzpk);
                u64 zi1 = fma2(px23, xz23, z2);
                float gin = hadd(fma2(px23, xn23, fma2(px01, xn01, binpk)));

                // r gate: 4 accumulators, depth 2
                u64 r0 = fma2(hp[0], wr[0], ri0); r0 = fma2(hp[4], wr[4], r0);
                u64 r1 = fma2(hp[1], wr[1], ri1); r1 = fma2(hp[5], wr[5], r1);
                u64 r2 = fma2(hp[2], wr[2], z2);  r2 = fma2(hp[6], wr[6], r2);
                u64 r3 = fma2(hp[3], wr[3], z2);  r3 = fma2(hp[7], wr[7], r3);
                float sr = hadd(add2(add2(r0,r1), add2(r2,r3)));
                // z gate
                u64 q0 = fma2(hp[0], wz[0], zi0); q0 = fma2(hp[4], wz[4], q0);
                u64 q1 = fma2(hp[1], wz[1], zi1); q1 = fma2(hp[5], wz[5], q1);
                u64 q2 = fma2(hp[2], wz[2], z2);  q2 = fma2(hp[6], wz[6], q2);
                u64 q3 = fma2(hp[3], wz[3], z2);  q3 = fma2(hp[7], wz[7], q3);
                float sz = hadd(add2(add2(q0,q1), add2(q2,q3)));
                // n gate (recurrent part pre-halved, incl. 0.5*bhn)
                u64 n0 = fma2(hp[0], wn[0], bhnpk); n0 = fma2(hp[4], wn[4], n0);
                u64 n1 = fma2(hp[1], wn[1], z2);    n1 = fma2(hp[5], wn[5], n1);
                u64 n2 = fma2(hp[2], wn[2], z2);    n2 = fma2(hp[6], wn[6], n2);
                u64 n3 = fma2(hp[3], wn[3], z2);    n3 = fma2(hp[7], wn[7], n3);
                float ghn = hadd(add2(add2(n0,n1), add2(n2,n3)));  // = 0.5*(h·Whn+bhn)

                float tr  = tanh_ap(sr);             // r = 0.5 + 0.5*tr
                float tz  = tanh_ap(sz);
                float zg  = fmaf(tz,  0.5f, 0.5f);
                float omz = fmaf(tz, -0.5f, 0.5f);
                float zh  = zg * hme;                // off the n-path
                float base = gin + ghn;
                float n = tanh_ap(fmaf(tr, ghn, base));
                hme = fmaf(n, omz, zh);
                sts_h(hbase + j*4, hme);
                ldh4(hbase, hp);                     // hp = h_{t+1}
            }
        }
    }

    // =================== DECODER ===================
    {
        const int v = j & 3;
        u64 wr[8], wz[8], wn[8], ow[8];
#pragma unroll
        for (int p = 0; p < 8; p++) {
            wr[p] = pk(0.5f*dWhh[j*16 + 2*p],      0.5f*dWhh[j*16 + 2*p+1]);
            wz[p] = pk(0.5f*dWhh[(16+j)*16 + 2*p], 0.5f*dWhh[(16+j)*16 + 2*p+1]);
            wn[p] = pk(0.5f*dWhh[(32+j)*16 + 2*p], 0.5f*dWhh[(32+j)*16 + 2*p+1]);
            ow[p] = pk(oW[v*16 + 2*p], oW[v*16 + 2*p+1]);
        }
        const float br   = 0.5f*(dbih[j]    + dbhh[j]);
        const float bz   = 0.5f*(dbih[16+j] + dbhh[16+j]);
        const float bin_ = dbih[32+j];
        const u64 bhnpk  = pk(0.5f*dbhh[32+j], 0.f);
        const u64 obpk   = pk(ob[v], 0.f);

        // precomputed feedback candidates: c -> bias + Wih[:,c]
        float crc[4], czc[4], cnc[4];
#pragma unroll
        for (int c = 0; c < 4; c++) {
            crc[c] = br   + 0.5f*dWih[j*4 + c];
            czc[c] = bz   + 0.5f*dWih[(16+j)*4 + c];
            cnc[c] = bin_ +      dWih[(32+j)*4 + c];
        }
        float cr = br, cz = bz, cn = bin_;     // t=0: x = 0

        u64 hp[8];
        sts_h(hbase + j*4, hme);
        ldh4(hbase, hp);                       // hp = enc hidden

        float lacc = 0.f;
        const float LOG2E = 1.4426950408889634f;
        const float LN2   = 0.6931471805599453f;

        for (int t4 = 0; t4 < SQ; ++t4) {
            int t4p = t4 + 8 < SQ ? t4 + 8 : SQ - 1;
            pf_l1(gp + t4p); pf_l1(gp + SQ + t4p); pf_l1(gp + 2*SQ + t4p); pf_l1(gp + 3*SQ + t4p);
            float4 xv0 = gp[t4], xv1 = gp[SQ + t4], xv2 = gp[2*SQ + t4], xv3 = gp[3*SQ + t4];
#pragma unroll
            for (int u = 0; u < 4; u++) {
                // ---- GRU gates from hp (h_t); scalar x-contribs added at tail ----
                u64 r0 = fma2(hp[0], wr[0], z2); r0 = fma2(hp[4], wr[4], r0);
                u64 r1 = fma2(hp[1], wr[1], z2); r1 = fma2(hp[5], wr[5], r1);
                u64 r2 = fma2(hp[2], wr[2], z2); r2 = fma2(hp[6], wr[6], r2);
                u64 r3 = fma2(hp[3], wr[3], z2); r3 = fma2(hp[7], wr[7], r3);
                float sr = hadd(add2(add2(r0,r1), add2(r2,r3))) + cr;

                u64 q0 = fma2(hp[0], wz[0], z2); q0 = fma2(hp[4], wz[4], q0);
                u64 q1 = fma2(hp[1], wz[1], z2); q1 = fma2(hp[5], wz[5], q1);
                u64 q2 = fma2(hp[2], wz[2], z2); q2 = fma2(hp[6], wz[6], q2);
                u64 q3 = fma2(hp[3], wz[3], z2); q3 = fma2(hp[7], wz[7], q3);
                float sz = hadd(add2(add2(q0,q1), add2(q2,q3))) + cz;

                u64 n0 = fma2(hp[0], wn[0], bhnpk); n0 = fma2(hp[4], wn[4], n0);
                u64 n1 = fma2(hp[1], wn[1], z2);    n1 = fma2(hp[5], wn[5], n1);
                u64 n2 = fma2(hp[2], wn[2], z2);    n2 = fma2(hp[6], wn[6], n2);
                u64 n3 = fma2(hp[3], wn[3], z2);    n3 = fma2(hp[7], wn[7], n3);
                float ghn = hadd(add2(add2(n0,n1), add2(n2,n3)));

                float tr  = tanh_ap(sr);
                float tz  = tanh_ap(sz);
                float zg  = fmaf(tz,  0.5f, 0.5f);
                float omz = fmaf(tz, -0.5f, 0.5f);
                float zh  = zg * hme;
                float base = cn + ghn;
                float n = tanh_ap(fmaf(tr, ghn, base));
                hme = fmaf(n, omz, zh);
                sts_h(hbase + j*4, hme);
                ldh4(hbase, hp);                 // hp = h_{t+1} (logits + next gates)

                // ---- logit for class v from fresh hp ----
                u64 o0 = fma2(hp[0], ow[0], obpk); o0 = fma2(hp[4], ow[4], o0);
                u64 o1 = fma2(hp[1], ow[1], z2);   o1 = fma2(hp[5], ow[5], o1);
                u64 o2 = fma2(hp[2], ow[2], z2);   o2 = fma2(hp[6], ow[6], o2);
                u64 o3 = fma2(hp[3], ow[3], z2);   o3 = fma2(hp[7], ow[7], o3);
                float outv = hadd(add2(add2(o0,o1), add2(o2,o3)));

                float l0 = __shfl_sync(0xffffffffu, outv, 0, 4);
                float l1 = __shfl_sync(0xffffffffu, outv, 1, 4);
                float l2 = __shfl_sync(0xffffffffu, outv, 2, 4);
                float l3 = __shfl_sync(0xffffffffu, outv, 3, 4);

                // argmax (first-max tie rule) + feedback select
                bool p01 = l1 > l0;  float m01 = fmaxf(l0, l1);
                bool p23 = l3 > l2;  float m23 = fmaxf(l2, l3);
                bool phi = m23 > m01; float mval = fmaxf(m01, m23);
                cr = phi ? (p23 ? crc[3] : crc[2]) : (p01 ? crc[1] : crc[0]);
                cz = phi ? (p23 ? czc[3] : czc[2]) : (p01 ? czc[1] : czc[0]);
                cn = phi ? (p23 ? cnc[3] : cnc[2]) : (p01 ? cnc[1] : cnc[0]);

                // logsumexp over 4 logits (lane-parallel, width-4 xor reduce)
                float e = ex2_ap((outv - mval) * LOG2E);
                e += __shfl_xor_sync(0xffffffffu, e, 1, 4);
                e += __shfl_xor_sync(0xffffffffu, e, 2, 4);
                float lse = lg2_ap(e) * LN2;

                // target = argmax(gt[t,b,:]) (first-max)
                float x0 = f4c(xv0,u), x1 = f4c(xv1,u), x2 = f4c(xv2,u), x3 = f4c(xv3,u);
                bool u01 = x1 > x0;  float t01 = fmaxf(x0, x1);
                bool u23 = x3 > x2;  float t23 = fmaxf(x2, x3);
                bool uhi = t23 > t01;
                float out_t = uhi ? (u23 ? l3 : l2) : (u01 ? l1 : l0);

                lacc += (mval + lse - out_t);
            }
        }
        if (lane == 0) g_loss[b] = lacc;
    }
}

// ---------------------------------------------------------------------------
__global__ void zero_kernel(float* __restrict__ out, long long n)
{
    long long n4 = n >> 2;
    float4* o4 = (float4*)out;
    long long i = (long long)blockIdx.x * blockDim.x + threadIdx.x;
    long long stride = (long long)gridDim.x * blockDim.x;
    float4 zz = make_float4(0.f, 0.f, 0.f, 0.f);
    for (; i < n4; i += stride) o4[i] = zz;
    if (blockIdx.x == 0 && threadIdx.x == 0)
        for (long long k = n4 << 2; k < n; k++) out[k] = 0.f;
}

__global__ void fin_kernel(float* __restrict__ out)
{
    __shared__ float s[BB];
    s[threadIdx.x] = g_loss[threadIdx.x];
    __syncthreads();
#pragma unroll
    for (int st = BB/2; st > 0; st >>= 1) {
        if ((int)threadIdx.x < st) s[threadIdx.x] += s[threadIdx.x + st];
        __syncthreads();
    }
    if (threadIdx.x == 0) out[0] = s[0] * (1.f / (float)BB);
}

// ---------------------------------------------------------------------------
extern "C" void kernel_launch(void* const* d_in, const int* in_sizes, int n_in,
                              void* d_out, int out_size)
{
    const float* gt   = (const float*)d_in[0];
    const float* eWih = (const float*)d_in[1];
    const float* eWhh = (const float*)d_in[2];
    const float* ebih = (const float*)d_in[3];
    const float* ebhh = (const float*)d_in[4];
    const float* dWih = (const float*)d_in[5];
    const float* dWhh = (const float*)d_in[6];
    const float* dbih = (const float*)d_in[7];
    const float* dbhh = (const float*)d_in[8];
    const float* oW   = (const float*)d_in[9];
    const float* ob   = (const float*)d_in[10];
    float* out = (float*)d_out;

    zero_kernel<<<512, 256>>>(out, (long long)out_size);
    fused_kernel<<<NBLOCKS, NTHREADS>>>(gt, eWih, eWhh, ebih, ebhh,
                                        dWih, dWhh, dbih, dbhh, oW, ob);
    fin_kernel<<<1, BB>>>(out);
}

// round 5
// speedup vs baseline: 1.9831x; 1.1449x over previous
#include <cuda_runtime.h>

#define HH 16
#define VV 4
#define BB 512
#define SS 8192
#define WPB 4                 // warps per block, 1 batch element per warp
#define NTHREADS (WPB*32)     // 128
#define NBLOCKS (BB/WPB)      // 128 blocks

__device__ float  g_loss[BB];
__device__ float4 g_logits[BB*SS];   // 64 MB scratch: out[b][t][0..3]

typedef unsigned long long u64;

__device__ __forceinline__ float tanh_ap(float x){ float y; asm("tanh.approx.f32 %0, %1;" : "=f"(y) : "f"(x)); return y; }
__device__ __forceinline__ u64 pk(float lo, float hi){ u64 d; asm("mov.b64 %0,{%1,%2};" : "=l"(d) : "f"(lo), "f"(hi)); return d; }
__device__ __forceinline__ u64 fma2(u64 a, u64 b, u64 c){ u64 d; asm("fma.rn.f32x2 %0,%1,%2,%3;" : "=l"(d) : "l"(a), "l"(b), "l"(c)); return d; }
__device__ __forceinline__ u64 add2(u64 a, u64 b){ u64 d; asm("add.rn.f32x2 %0,%1,%2;" : "=l"(d) : "l"(a), "l"(b)); return d; }
__device__ __forceinline__ float hadd(u64 a){ float x,y; asm("mov.b64 {%0,%1},%2;" : "=f"(x), "=f"(y) : "l"(a)); return x+y; }
__device__ __forceinline__ float f4c(float4 v, int u){ return u==0?v.x:(u==1?v.y:(u==2?v.z:v.w)); }

__device__ __forceinline__ void sts_h(unsigned addr, float v){
    asm volatile("st.shared.b32 [%0], %1;" :: "r"(addr), "f"(v));
}
__device__ __forceinline__ void ldh4(unsigned base, u64* hp){
    asm volatile("ld.shared.v2.b64 {%0,%1},[%2];"    : "=l"(hp[0]), "=l"(hp[1]) : "r"(base));
    asm volatile("ld.shared.v2.b64 {%0,%1},[%2+16];" : "=l"(hp[2]), "=l"(hp[3]) : "r"(base));
    asm volatile("ld.shared.v2.b64 {%0,%1},[%2+32];" : "=l"(hp[4]), "=l"(hp[5]) : "r"(base));
    asm volatile("ld.shared.v2.b64 {%0,%1},[%2+48];" : "=l"(hp[6]), "=l"(hp[7]) : "r"(base));
}

// ---------------------------------------------------------------------------
// Fused encoder + decoder recurrence. One batch element per warp.
// Decoder stores logits to g_logits; NLL computed by pass2_kernel.
// ---------------------------------------------------------------------------
__global__ void __launch_bounds__(NTHREADS, 1)
rnn_kernel(const float* __restrict__ gt,
           const float* __restrict__ eWih, const float* __restrict__ eWhh,
           const float* __restrict__ ebih, const float* __restrict__ ebhh,
           const float* __restrict__ dWih, const float* __restrict__ dWhh,
           const float* __restrict__ dbih, const float* __restrict__ dbhh,
           const float* __restrict__ oW,  const float* __restrict__ ob)
{
    __shared__ __align__(16) float sh[WPB*16];
    const int lane = threadIdx.x & 31;
    const int w    = threadIdx.x >> 5;
    const int j    = lane & 15;
    const int b    = blockIdx.x * WPB + w;
    const unsigned hbase = (unsigned)__cvta_generic_to_shared(&sh[w*16]);

    const float4* gp = (const float4*)(gt + (size_t)b * VV * SS);
    const int SQ = SS / 4;
    const u64 z2 = 0ULL;

    float hme = 0.f;

    // =================== ENCODER ===================
    {
        u64 wr[8], wz[8], wn[8];
#pragma unroll
        for (int p = 0; p < 8; p++) {
            wr[p] = pk(0.5f*eWhh[j*16 + 2*p],      0.5f*eWhh[j*16 + 2*p+1]);
            wz[p] = pk(0.5f*eWhh[(16+j)*16 + 2*p], 0.5f*eWhh[(16+j)*16 + 2*p+1]);
            wn[p] = pk(0.5f*eWhh[(32+j)*16 + 2*p], 0.5f*eWhh[(32+j)*16 + 2*p+1]);
        }
        const u64 xr01 = pk(0.5f*eWih[j*4+0],      0.5f*eWih[j*4+1]);
        const u64 xr23 = pk(0.5f*eWih[j*4+2],      0.5f*eWih[j*4+3]);
        const u64 xz01 = pk(0.5f*eWih[(16+j)*4+0], 0.5f*eWih[(16+j)*4+1]);
        const u64 xz23 = pk(0.5f*eWih[(16+j)*4+2], 0.5f*eWih[(16+j)*4+3]);
        const u64 xn01 = pk(     eWih[(32+j)*4+0],      eWih[(32+j)*4+1]);
        const u64 xn23 = pk(     eWih[(32+j)*4+2],      eWih[(32+j)*4+3]);
        const u64 brpk  = pk(0.5f*(ebih[j]    + ebhh[j]),    0.f);
        const u64 bzpk  = pk(0.5f*(ebih[16+j] + ebhh[16+j]), 0.f);
        const u64 binpk = pk(ebih[32+j], 0.f);
        const u64 bhnpk = pk(0.5f*ebhh[32+j], 0.f);

        u64 hp[8];
#pragma unroll
        for (int p = 0; p < 8; p++) hp[p] = 0ULL;   // h0 = 0

        // register double-buffer of gt (prefetch distance = 4 steps)
        float4 c0 = gp[0], c1 = gp[SQ], c2 = gp[2*SQ], c3 = gp[3*SQ];

        for (int t4 = 0; t4 < SQ; ++t4) {
            int tn = t4 + 1 < SQ ? t4 + 1 : t4;
            float4 n0 = gp[tn], n1 = gp[SQ + tn], n2 = gp[2*SQ + tn], n3 = gp[3*SQ + tn];
#pragma unroll
            for (int u = 0; u < 4; u++) {
                u64 px01 = pk(f4c(c0,u), f4c(c1,u));
                u64 px23 = pk(f4c(c2,u), f4c(c3,u));
                u64 ri0 = fma2(px01, xr01, brpk);
                u64 ri1 = fma2(px23, xr23, z2);
                u64 zi0 = fma2(px01, xz01, bzpk);
                u64 zi1 = fma2(px23, xz23, z2);
                float gin = hadd(fma2(px23, xn23, fma2(px01, xn01, binpk)));

                u64 r0 = fma2(hp[0], wr[0], ri0); r0 = fma2(hp[4], wr[4], r0);
                u64 r1 = fma2(hp[1], wr[1], ri1); r1 = fma2(hp[5], wr[5], r1);
                u64 r2 = fma2(hp[2], wr[2], z2);  r2 = fma2(hp[6], wr[6], r2);
                u64 r3 = fma2(hp[3], wr[3], z2);  r3 = fma2(hp[7], wr[7], r3);
                float sr = hadd(add2(add2(r0,r1), add2(r2,r3)));

                u64 q0 = fma2(hp[0], wz[0], zi0); q0 = fma2(hp[4], wz[4], q0);
                u64 q1 = fma2(hp[1], wz[1], zi1); q1 = fma2(hp[5], wz[5], q1);
                u64 q2 = fma2(hp[2], wz[2], z2);  q2 = fma2(hp[6], wz[6], q2);
                u64 q3 = fma2(hp[3], wz[3], z2);  q3 = fma2(hp[7], wz[7], q3);
                float sz = hadd(add2(add2(q0,q1), add2(q2,q3)));

                u64 n0a = fma2(hp[0], wn[0], bhnpk); n0a = fma2(hp[4], wn[4], n0a);
                u64 n1a = fma2(hp[1], wn[1], z2);    n1a = fma2(hp[5], wn[5], n1a);
                u64 n2a = fma2(hp[2], wn[2], z2);    n2a = fma2(hp[6], wn[6], n2a);
                u64 n3a = fma2(hp[3], wn[3], z2);    n3a = fma2(hp[7], wn[7], n3a);
                float ghn = hadd(add2(add2(n0a,n1a), add2(n2a,n3a)));

                float tr  = tanh_ap(sr);
                float tz  = tanh_ap(sz);
                float zg  = fmaf(tz,  0.5f, 0.5f);
                float omz = fmaf(tz, -0.5f, 0.5f);
                float zh  = zg * hme;
                float n = tanh_ap(fmaf(tr, ghn, gin + ghn));
                hme = fmaf(n, omz, zh);
                sts_h(hbase + j*4, hme);
                ldh4(hbase, hp);
            }
            c0 = n0; c1 = n1; c2 = n2; c3 = n3;
        }
    }

    // =================== DECODER (recurrence + argmax feedback only) ========
    {
        const int v = j & 3;
        u64 wr[8], wz[8], wn[8], ow[8];
#pragma unroll
        for (int p = 0; p < 8; p++) {
            wr[p] = pk(0.5f*dWhh[j*16 + 2*p],      0.5f*dWhh[j*16 + 2*p+1]);
            wz[p] = pk(0.5f*dWhh[(16+j)*16 + 2*p], 0.5f*dWhh[(16+j)*16 + 2*p+1]);
            wn[p] = pk(0.5f*dWhh[(32+j)*16 + 2*p], 0.5f*dWhh[(32+j)*16 + 2*p+1]);
            ow[p] = pk(oW[v*16 + 2*p], oW[v*16 + 2*p+1]);
        }
        const float br   = 0.5f*(dbih[j]    + dbhh[j]);
        const float bz   = 0.5f*(dbih[16+j] + dbhh[16+j]);
        const float bin_ = dbih[32+j];
        const u64 bhnpk  = pk(0.5f*dbhh[32+j], 0.f);
        const u64 obpk   = pk(ob[v], 0.f);

        float crc[4], czc[4], cnc[4];
#pragma unroll
        for (int c = 0; c < 4; c++) {
            crc[c] = br   + 0.5f*dWih[j*4 + c];
            czc[c] = bz   + 0.5f*dWih[(16+j)*4 + c];
            cnc[c] = bin_ +      dWih[(32+j)*4 + c];
        }
        float cr = br, cz = bz, cn = bin_;     // t=0: x = 0

        u64 hp[8];
        sts_h(hbase + j*4, hme);
        ldh4(hbase, hp);                       // hp = enc hidden

        float4* lp = &g_logits[(size_t)b * SS];

        for (int t = 0; t < SS; ++t) {
            // gates from hp = h_t
            u64 r0 = fma2(hp[0], wr[0], z2); r0 = fma2(hp[4], wr[4], r0);
            u64 r1 = fma2(hp[1], wr[1], z2); r1 = fma2(hp[5], wr[5], r1);
            u64 r2 = fma2(hp[2], wr[2], z2); r2 = fma2(hp[6], wr[6], r2);
            u64 r3 = fma2(hp[3], wr[3], z2); r3 = fma2(hp[7], wr[7], r3);
            float sr = hadd(add2(add2(r0,r1), add2(r2,r3))) + cr;

            u64 q0 = fma2(hp[0], wz[0], z2); q0 = fma2(hp[4], wz[4], q0);
            u64 q1 = fma2(hp[1], wz[1], z2); q1 = fma2(hp[5], wz[5], q1);
            u64 q2 = fma2(hp[2], wz[2], z2); q2 = fma2(hp[6], wz[6], q2);
            u64 q3 = fma2(hp[3], wz[3], z2); q3 = fma2(hp[7], wz[7], q3);
            float sz = hadd(add2(add2(q0,q1), add2(q2,q3))) + cz;

            u64 n0 = fma2(hp[0], wn[0], bhnpk); n0 = fma2(hp[4], wn[4], n0);
            u64 n1 = fma2(hp[1], wn[1], z2);    n1 = fma2(hp[5], wn[5], n1);
            u64 n2 = fma2(hp[2], wn[2], z2);    n2 = fma2(hp[6], wn[6], n2);
            u64 n3 = fma2(hp[3], wn[3], z2);    n3 = fma2(hp[7], wn[7], n3);
            float ghn = hadd(add2(add2(n0,n1), add2(n2,n3)));

            float tr  = tanh_ap(sr);
            float tz  = tanh_ap(sz);
            float zg  = fmaf(tz,  0.5f, 0.5f);
            float omz = fmaf(tz, -0.5f, 0.5f);
            float zh  = zg * hme;
            float n = tanh_ap(fmaf(tr, ghn, cn + ghn));
            hme = fmaf(n, omz, zh);
            sts_h(hbase + j*4, hme);
            ldh4(hbase, hp);                 // hp = h_{t+1}

            // logit for class v from fresh hp
            u64 o0 = fma2(hp[0], ow[0], obpk); o0 = fma2(hp[4], ow[4], o0);
            u64 o1 = fma2(hp[1], ow[1], z2);   o1 = fma2(hp[5], ow[5], o1);
            u64 o2 = fma2(hp[2], ow[2], z2);   o2 = fma2(hp[6], ow[6], o2);
            u64 o3 = fma2(hp[3], ow[3], z2);   o3 = fma2(hp[7], ow[7], o3);
            float outv = hadd(add2(add2(o0,o1), add2(o2,o3)));

            float l0 = __shfl_sync(0xffffffffu, outv, 0, 4);
            float l1 = __shfl_sync(0xffffffffu, outv, 1, 4);
            float l2 = __shfl_sync(0xffffffffu, outv, 2, 4);
            float l3 = __shfl_sync(0xffffffffu, outv, 3, 4);

            if (lane == 0) lp[t] = make_float4(l0, l1, l2, l3);

            // argmax (first-max) -> feedback select
            bool p01 = l1 > l0;  float m01 = fmaxf(l0, l1);
            bool p23 = l3 > l2;  float m23 = fmaxf(l2, l3);
            bool phi = m23 > m01;
            cr = phi ? (p23 ? crc[3] : crc[2]) : (p01 ? crc[1] : crc[0]);
            cz = phi ? (p23 ? czc[3] : czc[2]) : (p01 ? czc[1] : czc[0]);
            cn = phi ? (p23 ? cnc[3] : cnc[2]) : (p01 ? cnc[1] : cnc[0]);
        }
    }
}

// ---------------------------------------------------------------------------
// Pass 2: NLL from stored logits + targets from gt. One block per batch elem.
// ---------------------------------------------------------------------------
__global__ void __launch_bounds__(256)
pass2_kernel(const float* __restrict__ gt)
{
    const int b   = blockIdx.x;
    const int tid = threadIdx.x;
    const float4* lp = &g_logits[(size_t)b * SS];
    const float* g0 = gt + (size_t)b * VV * SS;

    float acc = 0.f;
    for (int t = tid; t < SS; t += 256) {
        float4 l = lp[t];
        float x0 = g0[t], x1 = g0[SS + t], x2 = g0[2*SS + t], x3 = g0[3*SS + t];
        // target = first-max argmax of gt
        bool u01 = x1 > x0;  float t01 = fmaxf(x0, x1);
        bool u23 = x3 > x2;  float t23 = fmaxf(x2, x3);
        bool uhi = t23 > t01;
        float lt = uhi ? (u23 ? l.w : l.z) : (u01 ? l.y : l.x);
        // stable log-sum-exp (precise)
        float m = fmaxf(fmaxf(l.x, l.y), fmaxf(l.z, l.w));
        float s = expf(l.x - m) + expf(l.y - m) + expf(l.z - m) + expf(l.w - m);
        acc += m + logf(s) - lt;
    }
    __shared__ float sred[256];
    sred[tid] = acc;
    __syncthreads();
#pragma unroll
    for (int st = 128; st > 0; st >>= 1) {
        if (tid < st) sred[tid] += sred[tid + st];
        __syncthreads();
    }
    if (tid == 0) g_loss[b] = sred[0];
}

// ---------------------------------------------------------------------------
__global__ void zero_kernel(float* __restrict__ out, long long n)
{
    long long n4 = n >> 2;
    float4* o4 = (float4*)out;
    long long i = (long long)blockIdx.x * blockDim.x + threadIdx.x;
    long long stride = (long long)gridDim.x * blockDim.x;
    float4 zz = make_float4(0.f, 0.f, 0.f, 0.f);
    for (; i < n4; i += stride) o4[i] = zz;
    if (blockIdx.x == 0 && threadIdx.x == 0)
        for (long long k = n4 << 2; k < n; k++) out[k] = 0.f;
}

__global__ void fin_kernel(float* __restrict__ out)
{
    __shared__ float s[BB];
    s[threadIdx.x] = g_loss[threadIdx.x];
    __syncthreads();
#pragma unroll
    for (int st = BB/2; st > 0; st >>= 1) {
        if ((int)threadIdx.x < st) s[threadIdx.x] += s[threadIdx.x + st];
        __syncthreads();
    }
    if (threadIdx.x == 0) out[0] = s[0] * (1.f / (float)BB);
}

// ---------------------------------------------------------------------------
extern "C" void kernel_launch(void* const* d_in, const int* in_sizes, int n_in,
                              void* d_out, int out_size)
{
    const float* gt   = (const float*)d_in[0];
    const float* eWih = (const float*)d_in[1];
    const float* eWhh = (const float*)d_in[2];
    const float* ebih = (const float*)d_in[3];
    const float* ebhh = (const float*)d_in[4];
    const float* dWih = (const float*)d_in[5];
    const float* dWhh = (const float*)d_in[6];
    const float* dbih = (const float*)d_in[7];
    const float* dbhh = (const float*)d_in[8];
    const float* oW   = (const float*)d_in[9];
    const float* ob   = (const float*)d_in[10];
    float* out = (float*)d_out;

    zero_kernel<<<512, 256>>>(out, (long long)out_size);
    rnn_kernel<<<NBLOCKS, NTHREADS>>>(gt, eWih, eWhh, ebih, ebhh,
                                      dWih, dWhh, dbih, dbhh, oW, ob);
    pass2_kernel<<<BB, 256>>>(gt);
    fin_kernel<<<1, BB>>>(out);
}